// round 1
// baseline (speedup 1.0000x reference)
#include <cuda_runtime.h>

// Adaptive threshold spike encoding.
// x: [B=32, F=65536] f32.  out: [B=32, T=32, F=65536] f32.
// Per element: acc += x; spike = (acc >= thr); acc = spike ? 0 : acc;
//              thr = thr*(1-rate) + rate*|x|.  T=32 steps.
// Each thread handles one float4 (4 feature-adjacent elements) and writes
// 32 float4 stores (one per timestep), coalesced across the warp.

#define TIMESTEPS 32
#define F_DIM 65536
#define F4_DIM (F_DIM / 4)      // 16384 float4 per feature row
#define RATE 0.1f
#define ONE_MINUS_RATE 0.9f
#define THR0 0.5f

__global__ void adaptive_threshold_kernel(const float4* __restrict__ x,
                                          float4* __restrict__ out,
                                          int n4) {
    int i = blockIdx.x * blockDim.x + threadIdx.x;
    if (i >= n4) return;

    float4 xv = x[i];

    // element index -> (batch, feature4)
    int e  = i << 2;              // element index of lane 0 of this float4
    int b  = e >> 16;             // / 65536
    int f4 = (e & (F_DIM - 1)) >> 2;

    float xx[4] = {xv.x, xv.y, xv.z, xv.w};
    float adapt[4], acc[4], thr[4];
#pragma unroll
    for (int l = 0; l < 4; l++) {
        adapt[l] = RATE * fabsf(xx[l]);
        acc[l]   = 0.0f;
        thr[l]   = THR0;
    }

    // out[b][t][f] : base of this (b, f4) column, stride F4_DIM per timestep
    float4* ob = out + (size_t)b * (TIMESTEPS * F4_DIM) + f4;

#pragma unroll
    for (int t = 0; t < TIMESTEPS; t++) {
        float s[4];
#pragma unroll
        for (int l = 0; l < 4; l++) {
            acc[l] = acc[l] + xx[l];
            bool m = (acc[l] >= thr[l]);
            s[l]   = m ? 1.0f : 0.0f;
            acc[l] = m ? 0.0f : acc[l];
            thr[l] = thr[l] * ONE_MINUS_RATE + adapt[l];
        }
        float4 sv;
        sv.x = s[0]; sv.y = s[1]; sv.z = s[2]; sv.w = s[3];
        ob[(size_t)t * F4_DIM] = sv;
    }
}

extern "C" void kernel_launch(void* const* d_in, const int* in_sizes, int n_in,
                              void* d_out, int out_size) {
    const float4* x = (const float4*)d_in[0];
    float4* out = (float4*)d_out;
    int n4 = in_sizes[0] / 4;     // 2,097,152 / 4 = 524,288
    int threads = 256;
    int blocks = (n4 + threads - 1) / threads;
    adaptive_threshold_kernel<<<blocks, threads>>>(x, out, n4);
}